// round 1
// baseline (speedup 1.0000x reference)
#include <cuda_runtime.h>
#include <stdint.h>

// Problem constants (from reference)
#define M_PAIRS 4096
#define T_LEN   512
#define D_DIM   512
#define N_NEG   64
#define N_CAND  65          // 1 positive + 64 negatives
#define SPAN    4094u       // m - 2
// multiplier for 32-bit randint: (2^16 % 4094)^2 % 4094 = 1024
// multiplier for 64-bit randint: (2^32 % 4094)^2 % 4094 = 512

// Device scratch (no allocations allowed)
__device__ float g_enc [M_PAIRS * D_DIM];   // normalized gathered encodings
__device__ float g_pred[M_PAIRS * D_DIM];   // normalized gathered predictions
__device__ float g_rowloss[M_PAIRS];
__device__ float g_rowacc [M_PAIRS];
__device__ int   g_is64;

// ---------------- Threefry-2x32 (20 rounds), exact JAX semantics ------------
__device__ __forceinline__ void tf2x32(uint32_t k0, uint32_t k1,
                                       uint32_t x0, uint32_t x1,
                                       uint32_t& o0, uint32_t& o1) {
    uint32_t ks2 = 0x1BD11BDAu ^ k0 ^ k1;
    x0 += k0; x1 += k1;
#define TF_RND(R) { x0 += x1; x1 = (x1 << (R)) | (x1 >> (32 - (R))); x1 ^= x0; }
    TF_RND(13) TF_RND(15) TF_RND(26) TF_RND(6)
    x0 += k1;  x1 += ks2 + 1u;
    TF_RND(17) TF_RND(29) TF_RND(16) TF_RND(24)
    x0 += ks2; x1 += k0 + 2u;
    TF_RND(13) TF_RND(15) TF_RND(26) TF_RND(6)
    x0 += k0;  x1 += k1 + 3u;
    TF_RND(17) TF_RND(29) TF_RND(16) TF_RND(24)
    x0 += k1;  x1 += ks2 + 4u;
    TF_RND(13) TF_RND(15) TF_RND(26) TF_RND(6)
    x0 += ks2; x1 += k0 + 5u;
#undef TF_RND
    o0 = x0; o1 = x1;
}

// ---------------- Kernel 0: mask_ids dtype probe ----------------------------
// int64 layout: (low32, 0) pairs -> all odd int32 words within the first
// 2*M words are zero. int32 layout: odd words are col values in [0,512),
// which cannot all be zero for 4096 random values.
__global__ void detect_dtype_kernel(const int* __restrict__ mask32) {
    __shared__ int any;
    if (threadIdx.x == 0) any = 0;
    __syncthreads();
    int acc = 0;
    for (int i = threadIdx.x; i < M_PAIRS; i += blockDim.x)
        acc |= mask32[2 * i + 1];
    if (acc) atomicOr(&any, 1);
    __syncthreads();
    if (threadIdx.x == 0) g_is64 = (any == 0) ? 1 : 0;
}

// ---------------- Kernel 1: gather + L2 normalize ---------------------------
// One block per row m; 128 threads; float4 per thread covers D=512.
__global__ void __launch_bounds__(128)
gather_norm_kernel(const float* __restrict__ pred,
                   const float* __restrict__ enc,
                   const void*  __restrict__ mask) {
    int m   = blockIdx.x;
    int tid = threadIdx.x;

    long long row, col;
    if (g_is64) {
        const long long* mm = (const long long*)mask;
        row = mm[2 * m]; col = mm[2 * m + 1];
    } else {
        const int* mm = (const int*)mask;
        row = mm[2 * m]; col = mm[2 * m + 1];
    }
    long long base = (row * (long long)T_LEN + col) * (long long)D_DIM;

    __shared__ float red[4];

    // --- encoded ---
    {
        const float4* src = (const float4*)(enc + base);
        float4 v = src[tid];
        float ssq = v.x*v.x + v.y*v.y + v.z*v.z + v.w*v.w;
        #pragma unroll
        for (int o = 16; o; o >>= 1) ssq += __shfl_xor_sync(0xFFFFFFFFu, ssq, o);
        if ((tid & 31) == 0) red[tid >> 5] = ssq;
        __syncthreads();
        float tot = red[0] + red[1] + red[2] + red[3];
        float inv = 1.0f / fmaxf(sqrtf(tot), 1e-12f);
        float4 o4 = make_float4(v.x*inv, v.y*inv, v.z*inv, v.w*inv);
        ((float4*)(g_enc + (size_t)m * D_DIM))[tid] = o4;
        __syncthreads();
    }
    // --- predicted ---
    {
        const float4* src = (const float4*)(pred + base);
        float4 v = src[tid];
        float ssq = v.x*v.x + v.y*v.y + v.z*v.z + v.w*v.w;
        #pragma unroll
        for (int o = 16; o; o >>= 1) ssq += __shfl_xor_sync(0xFFFFFFFFu, ssq, o);
        if ((tid & 31) == 0) red[tid >> 5] = ssq;
        __syncthreads();
        float tot = red[0] + red[1] + red[2] + red[3];
        float inv = 1.0f / fmaxf(sqrtf(tot), 1e-12f);
        float4 o4 = make_float4(v.x*inv, v.y*inv, v.z*inv, v.w*inv);
        ((float4*)(g_pred + (size_t)m * D_DIM))[tid] = o4;
    }
}

// ---------------- Kernel 2: per-row sims + LSE + argmax ---------------------
// One block per row m; 128 threads (4 warps). Negatives selected by exact
// JAX threefry (partitionable path), then 65 warp-parallel dot products
// against L2-resident normalized encodings.
__global__ void __launch_bounds__(128)
sim_kernel() {
    int m   = blockIdx.x;
    int tid = threadIdx.x;

    __shared__ float sp[D_DIM];
    __shared__ int   sel[N_CAND];
    __shared__ float sims[N_CAND];

    // stage pred row into smem
    ((float4*)sp)[tid] = ((const float4*)(g_pred + (size_t)m * D_DIM))[tid];

    if (tid < N_CAND) {
        if (tid == 0) {
            sel[0] = m;
        } else {
            // subkeys: foldlike split of key(42) = (0,42)
            uint32_t k1a, k1b, k2a, k2b;
            tf2x32(0u, 42u, 0u, 0u, k1a, k1b);
            tf2x32(0u, 42u, 0u, 1u, k2a, k2b);
            uint32_t t = (uint32_t)m * 64u + (uint32_t)(tid - 1);
            uint32_t a0, a1, b0, b1;
            tf2x32(k1a, k1b, 0u, t, a0, a1);
            tf2x32(k2a, k2b, 0u, t, b0, b1);
            uint32_t r;
            if (!g_is64) {
                // 32-bit randint: bits = x ^ y ; multiplier = 1024
                uint32_t hi = a0 ^ a1, lo = b0 ^ b1;
                r = ((hi % SPAN) * 1024u + (lo % SPAN)) % SPAN;
            } else {
                // 64-bit randint: bits = (x<<32)|y ; multiplier = 512
                unsigned long long hi = (((unsigned long long)a0) << 32) | a1;
                unsigned long long lo = (((unsigned long long)b0) << 32) | b1;
                unsigned long long rr = ((hi % 4094ull) * 512ull + (lo % 4094ull)) % 4094ull;
                r = (uint32_t)rr;
            }
            int s = (int)r + (((int)r >= m) ? 1 : 0);
            sel[tid] = s;
        }
    }
    __syncthreads();

    int warp = tid >> 5, lane = tid & 31;
    const float4* sp4 = (const float4*)sp;
    for (int c = warp; c < N_CAND; c += 4) {
        const float4* e4 = (const float4*)(g_enc + (size_t)sel[c] * D_DIM);
        float acc = 0.0f;
        #pragma unroll
        for (int j = 0; j < 4; j++) {
            float4 e = e4[lane + 32 * j];
            float4 p = sp4[lane + 32 * j];
            acc += e.x*p.x + e.y*p.y + e.z*p.z + e.w*p.w;
        }
        #pragma unroll
        for (int o = 16; o; o >>= 1) acc += __shfl_xor_sync(0xFFFFFFFFu, acc, o);
        if (lane == 0) sims[c] = acc / 0.1f;
    }
    __syncthreads();

    if (tid == 0) {
        float mx = sims[0];
        #pragma unroll 1
        for (int c = 1; c < N_CAND; c++) mx = fmaxf(mx, sims[c]);
        float s = 0.0f;
        #pragma unroll 1
        for (int c = 0; c < N_CAND; c++) s += expf(sims[c] - mx);
        float lse = mx + logf(s);
        g_rowloss[m] = lse - sims[0];
        int ok = 1;
        #pragma unroll 1
        for (int c = 1; c < N_CAND; c++) if (sims[c] > sims[0]) ok = 0;
        g_rowacc[m] = ok ? 1.0f : 0.0f;
    }
}

// ---------------- Kernel 3: deterministic reduction -------------------------
__global__ void __launch_bounds__(1024)
reduce_kernel(float* __restrict__ out, int out_size) {
    int tid = threadIdx.x;
    float sl = 0.0f, sa = 0.0f;
    for (int i = tid; i < M_PAIRS; i += 1024) {
        sl += g_rowloss[i];
        sa += g_rowacc[i];
    }
    __shared__ float bl[32], ba[32];
    #pragma unroll
    for (int o = 16; o; o >>= 1) {
        sl += __shfl_xor_sync(0xFFFFFFFFu, sl, o);
        sa += __shfl_xor_sync(0xFFFFFFFFu, sa, o);
    }
    if ((tid & 31) == 0) { bl[tid >> 5] = sl; ba[tid >> 5] = sa; }
    __syncthreads();
    if (tid < 32) {
        sl = bl[tid]; sa = ba[tid];
        #pragma unroll
        for (int o = 16; o; o >>= 1) {
            sl += __shfl_xor_sync(0xFFFFFFFFu, sl, o);
            sa += __shfl_xor_sync(0xFFFFFFFFu, sa, o);
        }
        if (tid == 0) {
            out[0] = sl / (float)M_PAIRS;
            if (out_size > 1) out[1] = sa / (float)M_PAIRS;
        }
    }
}

// ---------------- Launch ----------------------------------------------------
extern "C" void kernel_launch(void* const* d_in, const int* in_sizes, int n_in,
                              void* d_out, int out_size) {
    const float* pred = (const float*)d_in[0];  // input_predicted (B,T,D) f32
    const float* enc  = (const float*)d_in[1];  // input_encoded   (B,T,D) f32
    const void*  mask = d_in[2];                // mask_ids (M,2) int32 or int64

    detect_dtype_kernel<<<1, 256>>>((const int*)mask);
    gather_norm_kernel<<<M_PAIRS, 128>>>(pred, enc, mask);
    sim_kernel<<<M_PAIRS, 128>>>();
    reduce_kernel<<<1, 1024>>>((float*)d_out, out_size);
}

// round 2
// speedup vs baseline: 1.0447x; 1.0447x over previous
#include <cuda_runtime.h>
#include <cuda_bf16.h>
#include <stdint.h>

#define M_PAIRS 4096
#define T_LEN   512
#define D_DIM   512
#define N_CAND  65
#define SPAN    4094u

// Device scratch (no allocations allowed)
__device__ __nv_bfloat16 g_enc [M_PAIRS * D_DIM]; // normalized encodings (bf16)
__device__ float         g_pred[M_PAIRS * D_DIM]; // normalized predictions (fp32)
__device__ float         g_rowloss[M_PAIRS];
__device__ float         g_rowacc [M_PAIRS];
__device__ int           g_is64;
__device__ unsigned int  g_done;

// ---------------- Threefry-2x32 (20 rounds), exact JAX semantics ------------
__device__ __forceinline__ void tf2x32(uint32_t k0, uint32_t k1,
                                       uint32_t x0, uint32_t x1,
                                       uint32_t& o0, uint32_t& o1) {
    uint32_t ks2 = 0x1BD11BDAu ^ k0 ^ k1;
    x0 += k0; x1 += k1;
#define TF_RND(R) { x0 += x1; x1 = (x1 << (R)) | (x1 >> (32 - (R))); x1 ^= x0; }
    TF_RND(13) TF_RND(15) TF_RND(26) TF_RND(6)
    x0 += k1;  x1 += ks2 + 1u;
    TF_RND(17) TF_RND(29) TF_RND(16) TF_RND(24)
    x0 += ks2; x1 += k0 + 2u;
    TF_RND(13) TF_RND(15) TF_RND(26) TF_RND(6)
    x0 += k0;  x1 += k1 + 3u;
    TF_RND(17) TF_RND(29) TF_RND(16) TF_RND(24)
    x0 += k1;  x1 += ks2 + 4u;
    TF_RND(13) TF_RND(15) TF_RND(26) TF_RND(6)
    x0 += ks2; x1 += k0 + 5u;
#undef TF_RND
    o0 = x0; o1 = x1;
}

// ---------------- Kernel 0: dtype probe + counter reset ---------------------
// int64 mask: odd 32-bit words are hi words (all zero). int32 mask: odd words
// are cols in [0,512), cannot all be zero over 4096 samples.
__global__ void detect_dtype_kernel(const int* __restrict__ mask32) {
    __shared__ int any;
    if (threadIdx.x == 0) { any = 0; g_done = 0u; }
    __syncthreads();
    int acc = 0;
    for (int i = threadIdx.x; i < M_PAIRS; i += blockDim.x)
        acc |= mask32[2 * i + 1];
    if (acc) atomicOr(&any, 1);
    __syncthreads();
    if (threadIdx.x == 0) g_is64 = (any == 0) ? 1 : 0;
}

// ---------------- Kernel 1: gather + L2 normalize ---------------------------
__global__ void __launch_bounds__(128)
gather_norm_kernel(const float* __restrict__ pred,
                   const float* __restrict__ enc,
                   const void*  __restrict__ mask) {
    int m   = blockIdx.x;
    int tid = threadIdx.x;

    long long row, col;
    if (g_is64) {
        const long long* mm = (const long long*)mask;
        row = mm[2 * m]; col = mm[2 * m + 1];
    } else {
        const int* mm = (const int*)mask;
        row = mm[2 * m]; col = mm[2 * m + 1];
    }
    long long base = (row * (long long)T_LEN + col) * (long long)D_DIM;

    __shared__ float red[4];

    // --- encoded -> bf16 ---
    {
        const float4* src = (const float4*)(enc + base);
        float4 v = src[tid];
        float ssq = v.x*v.x + v.y*v.y + v.z*v.z + v.w*v.w;
        #pragma unroll
        for (int o = 16; o; o >>= 1) ssq += __shfl_xor_sync(0xFFFFFFFFu, ssq, o);
        if ((tid & 31) == 0) red[tid >> 5] = ssq;
        __syncthreads();
        float tot = red[0] + red[1] + red[2] + red[3];
        float inv = 1.0f / fmaxf(sqrtf(tot), 1e-12f);
        __nv_bfloat162 b0 = __floats2bfloat162_rn(v.x * inv, v.y * inv);
        __nv_bfloat162 b1 = __floats2bfloat162_rn(v.z * inv, v.w * inv);
        uint32_t u0 = *reinterpret_cast<uint32_t*>(&b0);
        uint32_t u1 = *reinterpret_cast<uint32_t*>(&b1);
        ((uint2*)(g_enc + (size_t)m * D_DIM))[tid] = make_uint2(u0, u1);
        __syncthreads();
    }
    // --- predicted -> fp32 ---
    {
        const float4* src = (const float4*)(pred + base);
        float4 v = src[tid];
        float ssq = v.x*v.x + v.y*v.y + v.z*v.z + v.w*v.w;
        #pragma unroll
        for (int o = 16; o; o >>= 1) ssq += __shfl_xor_sync(0xFFFFFFFFu, ssq, o);
        if ((tid & 31) == 0) red[tid >> 5] = ssq;
        __syncthreads();
        float tot = red[0] + red[1] + red[2] + red[3];
        float inv = 1.0f / fmaxf(sqrtf(tot), 1e-12f);
        float4 o4 = make_float4(v.x*inv, v.y*inv, v.z*inv, v.w*inv);
        ((float4*)(g_pred + (size_t)m * D_DIM))[tid] = o4;
    }
}

// ---------------- Kernel 2: sims + LSE + argmax + fused final reduce --------
__global__ void __launch_bounds__(128)
sim_kernel(float* __restrict__ out, int out_size) {
    int m    = blockIdx.x;
    int tid  = threadIdx.x;
    int warp = tid >> 5, lane = tid & 31;

    __shared__ int   sel[N_CAND];
    __shared__ float sims[N_CAND];

    // ---- negative selection via exact JAX threefry ----
    if (tid < N_CAND) {
        if (tid == 0) {
            sel[0] = m;
        } else {
            uint32_t k1a, k1b, k2a, k2b;
            tf2x32(0u, 42u, 0u, 0u, k1a, k1b);
            tf2x32(0u, 42u, 0u, 1u, k2a, k2b);
            uint32_t t = (uint32_t)m * 64u + (uint32_t)(tid - 1);
            uint32_t a0, a1, b0, b1;
            tf2x32(k1a, k1b, 0u, t, a0, a1);
            tf2x32(k2a, k2b, 0u, t, b0, b1);
            uint32_t r;
            if (!g_is64) {
                uint32_t hi = a0 ^ a1, lo = b0 ^ b1;
                r = ((hi % SPAN) * 1024u + (lo % SPAN)) % SPAN;
            } else {
                unsigned long long hi = (((unsigned long long)a0) << 32) | a1;
                unsigned long long lo = (((unsigned long long)b0) << 32) | b1;
                r = (uint32_t)(((hi % 4094ull) * 512ull + (lo % 4094ull)) % 4094ull);
            }
            sel[tid] = (int)r + (((int)r >= m) ? 1 : 0);
        }
    }

    // ---- stage this lane's 16 pred elements into registers ----
    // element range handled by lane: {j*256 + lane*8 + k : j in 0..1, k in 0..7}
    float p[2][8];
    {
        const float4* p4 = (const float4*)(g_pred + (size_t)m * D_DIM);
        #pragma unroll
        for (int j = 0; j < 2; j++) {
            float4 a = p4[j * 64 + lane * 2];
            float4 b = p4[j * 64 + lane * 2 + 1];
            p[j][0] = a.x; p[j][1] = a.y; p[j][2] = a.z; p[j][3] = a.w;
            p[j][4] = b.x; p[j][5] = b.y; p[j][6] = b.z; p[j][7] = b.w;
        }
    }
    __syncthreads();

    // ---- 65 dot products, one candidate per warp per iteration ----
    #pragma unroll 1
    for (int c = warp; c < N_CAND; c += 4) {
        const uint4* e8 = (const uint4*)(g_enc + (size_t)sel[c] * D_DIM);
        float acc = 0.0f;
        #pragma unroll
        for (int j = 0; j < 2; j++) {
            uint4 v = e8[j * 32 + lane];   // 8 bf16
            __nv_bfloat162 h0 = *reinterpret_cast<__nv_bfloat162*>(&v.x);
            __nv_bfloat162 h1 = *reinterpret_cast<__nv_bfloat162*>(&v.y);
            __nv_bfloat162 h2 = *reinterpret_cast<__nv_bfloat162*>(&v.z);
            __nv_bfloat162 h3 = *reinterpret_cast<__nv_bfloat162*>(&v.w);
            float2 f0 = __bfloat1622float2(h0);
            float2 f1 = __bfloat1622float2(h1);
            float2 f2 = __bfloat1622float2(h2);
            float2 f3 = __bfloat1622float2(h3);
            acc = fmaf(f0.x, p[j][0], acc);
            acc = fmaf(f0.y, p[j][1], acc);
            acc = fmaf(f1.x, p[j][2], acc);
            acc = fmaf(f1.y, p[j][3], acc);
            acc = fmaf(f2.x, p[j][4], acc);
            acc = fmaf(f2.y, p[j][5], acc);
            acc = fmaf(f3.x, p[j][6], acc);
            acc = fmaf(f3.y, p[j][7], acc);
        }
        #pragma unroll
        for (int o = 16; o; o >>= 1) acc += __shfl_xor_sync(0xFFFFFFFFu, acc, o);
        if (lane == 0) sims[c] = acc * 10.0f;   // / TEMPERATURE
    }
    __syncthreads();

    // ---- per-row LSE / argmax ----
    if (tid == 0) {
        float mx = sims[0];
        #pragma unroll 1
        for (int c = 1; c < N_CAND; c++) mx = fmaxf(mx, sims[c]);
        float s = 0.0f;
        #pragma unroll 1
        for (int c = 0; c < N_CAND; c++) s += expf(sims[c] - mx);
        g_rowloss[m] = mx + logf(s) - sims[0];
        int ok = 1;
        #pragma unroll 1
        for (int c = 1; c < N_CAND; c++) if (sims[c] > sims[0]) ok = 0;
        g_rowacc[m] = ok ? 1.0f : 0.0f;
    }

    // ---- fused deterministic final reduction (last block) ----
    __shared__ bool last;
    __threadfence();
    if (tid == 0) {
        unsigned v = atomicAdd(&g_done, 1u);
        last = (v == (unsigned)(M_PAIRS - 1));
    }
    __syncthreads();
    if (!last) return;
    __threadfence();

    float sl = 0.0f, sa = 0.0f;
    #pragma unroll 1
    for (int i = tid; i < M_PAIRS; i += 128) {
        sl += g_rowloss[i];
        sa += g_rowacc[i];
    }
    __shared__ float bl[4], ba[4];
    #pragma unroll
    for (int o = 16; o; o >>= 1) {
        sl += __shfl_xor_sync(0xFFFFFFFFu, sl, o);
        sa += __shfl_xor_sync(0xFFFFFFFFu, sa, o);
    }
    if (lane == 0) { bl[warp] = sl; ba[warp] = sa; }
    __syncthreads();
    if (tid == 0) {
        float tl = bl[0] + bl[1] + bl[2] + bl[3];
        float ta = ba[0] + ba[1] + ba[2] + ba[3];
        out[0] = tl / (float)M_PAIRS;
        if (out_size > 1) out[1] = ta / (float)M_PAIRS;
    }
}

// ---------------- Launch ----------------------------------------------------
extern "C" void kernel_launch(void* const* d_in, const int* in_sizes, int n_in,
                              void* d_out, int out_size) {
    const float* pred = (const float*)d_in[0];
    const float* enc  = (const float*)d_in[1];
    const void*  mask = d_in[2];

    detect_dtype_kernel<<<1, 256>>>((const int*)mask);
    gather_norm_kernel<<<M_PAIRS, 128>>>(pred, enc, mask);
    sim_kernel<<<M_PAIRS, 128>>>((float*)d_out, out_size);
}

// round 3
// speedup vs baseline: 1.5305x; 1.4649x over previous
#include <cuda_runtime.h>
#include <cuda_bf16.h>
#include <stdint.h>

#define M_PAIRS 4096
#define T_LEN   512
#define D_DIM   512
#define N_CAND  65
#define SPAN    4094u

// Device scratch (no allocations allowed)
__device__ __nv_bfloat16 g_enc [M_PAIRS * D_DIM];
__device__ float         g_pred[M_PAIRS * D_DIM];
__device__ float         g_rowloss[M_PAIRS];
__device__ float         g_rowacc [M_PAIRS];
__device__ int           g_is64;
__device__ unsigned int  g_cnt1[64];
__device__ unsigned int  g_cnt2;

// ---------------- Threefry-2x32 (20 rounds), exact JAX semantics ------------
struct TFK { uint32_t a, b; };

__host__ __device__ constexpr TFK tf2x32_c(uint32_t k0, uint32_t k1,
                                           uint32_t x0, uint32_t x1) {
    uint32_t ks2 = 0x1BD11BDAu ^ k0 ^ k1;
    x0 += k0; x1 += k1;
#define TF_RND(R) { x0 += x1; x1 = (x1 << (R)) | (x1 >> (32 - (R))); x1 ^= x0; }
    TF_RND(13) TF_RND(15) TF_RND(26) TF_RND(6)
    x0 += k1;  x1 += ks2 + 1u;
    TF_RND(17) TF_RND(29) TF_RND(16) TF_RND(24)
    x0 += ks2; x1 += k0 + 2u;
    TF_RND(13) TF_RND(15) TF_RND(26) TF_RND(6)
    x0 += k0;  x1 += k1 + 3u;
    TF_RND(17) TF_RND(29) TF_RND(16) TF_RND(24)
    x0 += k1;  x1 += ks2 + 4u;
    TF_RND(13) TF_RND(15) TF_RND(26) TF_RND(6)
    x0 += ks2; x1 += k0 + 5u;
#undef TF_RND
    return TFK{x0, x1};
}

// split(key(42)) subkeys — folded to immediates at compile time
__device__ constexpr TFK SK1 = tf2x32_c(0u, 42u, 0u, 0u);
__device__ constexpr TFK SK2 = tf2x32_c(0u, 42u, 0u, 1u);

__device__ __forceinline__ TFK tf2x32(uint32_t k0, uint32_t k1,
                                      uint32_t x0, uint32_t x1) {
    return tf2x32_c(k0, k1, x0, x1);
}

// ---------------- Kernel 0: dtype probe + counter reset ---------------------
__global__ void __launch_bounds__(1024)
detect_dtype_kernel(const int4* __restrict__ mask4) {
    __shared__ int any;
    int tid = threadIdx.x;
    if (tid == 0) any = 0;
    if (tid < 64) g_cnt1[tid] = 0u;
    if (tid == 64) g_cnt2 = 0u;
    __syncthreads();
    // 4096 pairs = 8192 int32 = 2048 int4; odd words = col (i32) / hi (i64)
    int4 a = mask4[tid];
    int4 b = mask4[tid + 1024];
    int acc = a.y | a.w | b.y | b.w;
    if (acc) atomicOr(&any, 1);
    __syncthreads();
    if (tid == 0) g_is64 = (any == 0) ? 1 : 0;
}

// ---------------- Kernel 1: gather + L2 normalize (enc/pred in parallel) ----
__global__ void __launch_bounds__(256)
gather_norm_kernel(const float* __restrict__ pred,
                   const float* __restrict__ enc,
                   const void*  __restrict__ mask) {
    int m    = blockIdx.x;
    int tid  = threadIdx.x;
    int half = tid >> 7;        // 0: encoded, 1: predicted
    int ht   = tid & 127;
    int warp = tid >> 5, lane = tid & 31;

    long long row, col;
    if (g_is64) {
        const long long* mm = (const long long*)mask;
        row = mm[2 * m]; col = mm[2 * m + 1];
    } else {
        const int* mm = (const int*)mask;
        row = mm[2 * m]; col = mm[2 * m + 1];
    }
    long long base = (row * (long long)T_LEN + col) * (long long)D_DIM;

    __shared__ float red[8];

    const float* src = half ? pred : enc;
    float4 v = ((const float4*)(src + base))[ht];
    float ssq = v.x*v.x + v.y*v.y + v.z*v.z + v.w*v.w;
    #pragma unroll
    for (int o = 16; o; o >>= 1) ssq += __shfl_xor_sync(0xFFFFFFFFu, ssq, o);
    if (lane == 0) red[warp] = ssq;
    __syncthreads();
    float tot = red[half * 4 + 0] + red[half * 4 + 1]
              + red[half * 4 + 2] + red[half * 4 + 3];
    float inv = 1.0f / fmaxf(sqrtf(tot), 1e-12f);
    if (half == 0) {
        __nv_bfloat162 b0 = __floats2bfloat162_rn(v.x * inv, v.y * inv);
        __nv_bfloat162 b1 = __floats2bfloat162_rn(v.z * inv, v.w * inv);
        uint32_t u0 = *reinterpret_cast<uint32_t*>(&b0);
        uint32_t u1 = *reinterpret_cast<uint32_t*>(&b1);
        ((uint2*)(g_enc + (size_t)m * D_DIM))[ht] = make_uint2(u0, u1);
    } else {
        ((float4*)(g_pred + (size_t)m * D_DIM))[ht] =
            make_float4(v.x*inv, v.y*inv, v.z*inv, v.w*inv);
    }
}

// ---------------- candidate dot helper --------------------------------------
__device__ __forceinline__ float cand_dot(const uint4* __restrict__ e8,
                                          int lane, const float p[2][8]) {
    float acc = 0.0f;
    #pragma unroll
    for (int j = 0; j < 2; j++) {
        uint4 v = e8[j * 32 + lane];
        float2 f0 = __bfloat1622float2(*reinterpret_cast<__nv_bfloat162*>(&v.x));
        float2 f1 = __bfloat1622float2(*reinterpret_cast<__nv_bfloat162*>(&v.y));
        float2 f2 = __bfloat1622float2(*reinterpret_cast<__nv_bfloat162*>(&v.z));
        float2 f3 = __bfloat1622float2(*reinterpret_cast<__nv_bfloat162*>(&v.w));
        acc = fmaf(f0.x, p[j][0], acc);  acc = fmaf(f0.y, p[j][1], acc);
        acc = fmaf(f1.x, p[j][2], acc);  acc = fmaf(f1.y, p[j][3], acc);
        acc = fmaf(f2.x, p[j][4], acc);  acc = fmaf(f2.y, p[j][5], acc);
        acc = fmaf(f3.x, p[j][6], acc);  acc = fmaf(f3.y, p[j][7], acc);
    }
    return acc;
}

// ---------------- Kernel 2: sims + LSE + argmax + tree-fused reduce ---------
__global__ void __launch_bounds__(256)
sim_kernel(float* __restrict__ out, int out_size) {
    int m    = blockIdx.x;
    int tid  = threadIdx.x;
    int warp = tid >> 5, lane = tid & 31;

    __shared__ int   sel[N_CAND];
    __shared__ float sims[N_CAND];

    // ---- negative selection (exact JAX threefry, subkeys constant-folded) --
    if (tid < N_CAND) {
        if (tid == 0) {
            sel[0] = m;
        } else {
            uint32_t t = (uint32_t)m * 64u + (uint32_t)(tid - 1);
            TFK A = tf2x32(SK1.a, SK1.b, 0u, t);
            TFK B = tf2x32(SK2.a, SK2.b, 0u, t);
            uint32_t r;
            if (!g_is64) {
                uint32_t hi = A.a ^ A.b, lo = B.a ^ B.b;
                r = ((hi % SPAN) * 1024u + (lo % SPAN)) % SPAN;
            } else {
                unsigned long long hi = (((unsigned long long)A.a) << 32) | A.b;
                unsigned long long lo = (((unsigned long long)B.a) << 32) | B.b;
                r = (uint32_t)(((hi % 4094ull) * 512ull + (lo % 4094ull)) % 4094ull);
            }
            sel[tid] = (int)r + (((int)r >= m) ? 1 : 0);
        }
    }

    // ---- stage this lane's 16 pred elements into registers ----
    float p[2][8];
    {
        const float4* p4 = (const float4*)(g_pred + (size_t)m * D_DIM);
        #pragma unroll
        for (int j = 0; j < 2; j++) {
            float4 a = p4[j * 64 + lane * 2];
            float4 b = p4[j * 64 + lane * 2 + 1];
            p[j][0] = a.x; p[j][1] = a.y; p[j][2] = a.z; p[j][3] = a.w;
            p[j][4] = b.x; p[j][5] = b.y; p[j][6] = b.z; p[j][7] = b.w;
        }
    }
    __syncthreads();

    // ---- 65 dots, 8 warps, 2 candidates in flight per warp ----
    {
        int c = warp;
        while (c + 8 < N_CAND) {
            const uint4* eA = (const uint4*)(g_enc + (size_t)sel[c]     * D_DIM);
            const uint4* eB = (const uint4*)(g_enc + (size_t)sel[c + 8] * D_DIM);
            float a0 = cand_dot(eA, lane, p);
            float a1 = cand_dot(eB, lane, p);
            #pragma unroll
            for (int o = 16; o; o >>= 1) {
                a0 += __shfl_xor_sync(0xFFFFFFFFu, a0, o);
                a1 += __shfl_xor_sync(0xFFFFFFFFu, a1, o);
            }
            if (lane == 0) { sims[c] = a0 * 10.0f; sims[c + 8] = a1 * 10.0f; }
            c += 16;
        }
        if (c < N_CAND) {
            const uint4* eA = (const uint4*)(g_enc + (size_t)sel[c] * D_DIM);
            float a0 = cand_dot(eA, lane, p);
            #pragma unroll
            for (int o = 16; o; o >>= 1) a0 += __shfl_xor_sync(0xFFFFFFFFu, a0, o);
            if (lane == 0) sims[c] = a0 * 10.0f;
        }
    }
    __syncthreads();

    // ---- warp-parallel LSE / argmax (warp 0) ----
    if (warp == 0) {
        float v0 = sims[lane];
        float v1 = sims[lane + 32];
        float v2 = (lane == 0) ? sims[64] : -3.4e38f;
        float mx = fmaxf(fmaxf(v0, v1), v2);
        #pragma unroll
        for (int o = 16; o; o >>= 1) mx = fmaxf(mx, __shfl_xor_sync(0xFFFFFFFFu, mx, o));
        float s = expf(v0 - mx) + expf(v1 - mx) + ((lane == 0) ? expf(v2 - mx) : 0.0f);
        #pragma unroll
        for (int o = 16; o; o >>= 1) s += __shfl_xor_sync(0xFFFFFFFFu, s, o);
        if (lane == 0) {
            float s0 = sims[0];
            g_rowloss[m] = mx + logf(s) - s0;
            g_rowacc[m]  = (s0 >= mx) ? 1.0f : 0.0f;  // argmax==0 <=> sims[0]==max
        }
    }

    // ---- two-level arrival tree + fused deterministic final reduce ----
    __shared__ bool last;
    __syncthreads();
    __threadfence();
    if (tid == 0) {
        bool l = false;
        if (atomicAdd(&g_cnt1[m >> 6], 1u) == 63u) {
            if (atomicAdd(&g_cnt2, 1u) == 63u) l = true;
        }
        last = l;
    }
    __syncthreads();
    if (!last) return;
    __threadfence();

    float sl = 0.0f, sa = 0.0f;
    #pragma unroll
    for (int k = 0; k < M_PAIRS / 256; k++) {
        int i = k * 256 + tid;
        sl += g_rowloss[i];
        sa += g_rowacc[i];
    }
    __shared__ float bl[8], ba[8];
    #pragma unroll
    for (int o = 16; o; o >>= 1) {
        sl += __shfl_xor_sync(0xFFFFFFFFu, sl, o);
        sa += __shfl_xor_sync(0xFFFFFFFFu, sa, o);
    }
    if (lane == 0) { bl[warp] = sl; ba[warp] = sa; }
    __syncthreads();
    if (tid == 0) {
        float tl = 0.0f, ta = 0.0f;
        #pragma unroll
        for (int w = 0; w < 8; w++) { tl += bl[w]; ta += ba[w]; }
        out[0] = tl / (float)M_PAIRS;
        if (out_size > 1) out[1] = ta / (float)M_PAIRS;
    }
}

// ---------------- Launch ----------------------------------------------------
extern "C" void kernel_launch(void* const* d_in, const int* in_sizes, int n_in,
                              void* d_out, int out_size) {
    const float* pred = (const float*)d_in[0];
    const float* enc  = (const float*)d_in[1];
    const void*  mask = d_in[2];

    detect_dtype_kernel<<<1, 1024>>>((const int4*)mask);
    gather_norm_kernel<<<M_PAIRS, 256>>>(pred, enc, mask);
    sim_kernel<<<M_PAIRS, 256>>>((float*)d_out, out_size);
}

// round 4
// speedup vs baseline: 1.5675x; 1.0242x over previous
#include <cuda_runtime.h>
#include <cuda_bf16.h>
#include <stdint.h>

#define M_PAIRS 4096
#define T_LEN   512
#define D_DIM   512
#define N_CAND  65
#define SPAN    4094u

// Device scratch (no allocations allowed). Zero-initialized at module load;
// counters are self-resetting (last sim block restores them), so every graph
// replay sees clean state.
__device__ __nv_bfloat16 g_enc [M_PAIRS * D_DIM];
__device__ float         g_pred[M_PAIRS * D_DIM];
__device__ float         g_rowloss[M_PAIRS];
__device__ float         g_rowacc [M_PAIRS];
__device__ int           g_is64;
__device__ unsigned int  g_cnt1[64];
__device__ unsigned int  g_cnt2;

// ---------------- Threefry-2x32 (20 rounds), exact JAX semantics ------------
struct TFK { uint32_t a, b; };

__host__ __device__ constexpr TFK tf2x32_c(uint32_t k0, uint32_t k1,
                                           uint32_t x0, uint32_t x1) {
    uint32_t ks2 = 0x1BD11BDAu ^ k0 ^ k1;
    x0 += k0; x1 += k1;
#define TF_RND(R) { x0 += x1; x1 = (x1 << (R)) | (x1 >> (32 - (R))); x1 ^= x0; }
    TF_RND(13) TF_RND(15) TF_RND(26) TF_RND(6)
    x0 += k1;  x1 += ks2 + 1u;
    TF_RND(17) TF_RND(29) TF_RND(16) TF_RND(24)
    x0 += ks2; x1 += k0 + 2u;
    TF_RND(13) TF_RND(15) TF_RND(26) TF_RND(6)
    x0 += k0;  x1 += k1 + 3u;
    TF_RND(17) TF_RND(29) TF_RND(16) TF_RND(24)
    x0 += k1;  x1 += ks2 + 4u;
    TF_RND(13) TF_RND(15) TF_RND(26) TF_RND(6)
    x0 += ks2; x1 += k0 + 5u;
#undef TF_RND
    return TFK{x0, x1};
}

// split(key(42)) subkeys — folded to immediates at compile time
__device__ constexpr TFK SK1 = tf2x32_c(0u, 42u, 0u, 0u);
__device__ constexpr TFK SK2 = tf2x32_c(0u, 42u, 0u, 1u);

// ---------------- inline dtype probe (warp-collective, fixed 512B window) ---
// int32 mask: odd words are cols in [0,512) — 64 random cols can't all be 0.
// int64 mask: odd words are hi-words of non-negative row/col — always 0.
__device__ __forceinline__ int detect_is64_warp(const int4* __restrict__ mask4,
                                                int lane) {
    int4 w = mask4[lane];                 // words [0,128): 64 odd-word samples
    unsigned any = __ballot_sync(0xFFFFFFFFu, (w.y | w.w) != 0);
    return (any == 0u) ? 1 : 0;
}

// ---------------- Kernel 1: gather + L2 normalize (enc/pred in parallel) ----
__global__ void __launch_bounds__(256)
gather_norm_kernel(const float* __restrict__ pred,
                   const float* __restrict__ enc,
                   const void*  __restrict__ mask) {
    int m    = blockIdx.x;
    int tid  = threadIdx.x;
    int half = tid >> 7;        // 0: encoded, 1: predicted
    int ht   = tid & 127;
    int warp = tid >> 5, lane = tid & 31;

    __shared__ int   s_is64;
    __shared__ float red[8];

    if (warp == 0) {
        int is64 = detect_is64_warp((const int4*)mask, lane);
        if (lane == 0) {
            s_is64 = is64;
            if (m == 0) g_is64 = is64;   // publish for sim_kernel (next launch)
        }
    }
    __syncthreads();

    long long row, col;
    if (s_is64) {
        const long long* mm = (const long long*)mask;
        row = mm[2 * m]; col = mm[2 * m + 1];
    } else {
        const int* mm = (const int*)mask;
        row = mm[2 * m]; col = mm[2 * m + 1];
    }
    long long base = (row * (long long)T_LEN + col) * (long long)D_DIM;

    const float* src = half ? pred : enc;
    float4 v = ((const float4*)(src + base))[ht];
    float ssq = v.x*v.x + v.y*v.y + v.z*v.z + v.w*v.w;
    #pragma unroll
    for (int o = 16; o; o >>= 1) ssq += __shfl_xor_sync(0xFFFFFFFFu, ssq, o);
    if (lane == 0) red[warp] = ssq;
    __syncthreads();
    float tot = red[half * 4 + 0] + red[half * 4 + 1]
              + red[half * 4 + 2] + red[half * 4 + 3];
    float inv = 1.0f / fmaxf(sqrtf(tot), 1e-12f);
    if (half == 0) {
        __nv_bfloat162 b0 = __floats2bfloat162_rn(v.x * inv, v.y * inv);
        __nv_bfloat162 b1 = __floats2bfloat162_rn(v.z * inv, v.w * inv);
        uint32_t u0 = *reinterpret_cast<uint32_t*>(&b0);
        uint32_t u1 = *reinterpret_cast<uint32_t*>(&b1);
        ((uint2*)(g_enc + (size_t)m * D_DIM))[ht] = make_uint2(u0, u1);
    } else {
        ((float4*)(g_pred + (size_t)m * D_DIM))[ht] =
            make_float4(v.x*inv, v.y*inv, v.z*inv, v.w*inv);
    }
}

// ---------------- candidate dot helper --------------------------------------
__device__ __forceinline__ float cand_dot(const uint4* __restrict__ e8,
                                          int lane, const float p[2][8]) {
    float acc = 0.0f;
    #pragma unroll
    for (int j = 0; j < 2; j++) {
        uint4 v = e8[j * 32 + lane];
        float2 f0 = __bfloat1622float2(*reinterpret_cast<__nv_bfloat162*>(&v.x));
        float2 f1 = __bfloat1622float2(*reinterpret_cast<__nv_bfloat162*>(&v.y));
        float2 f2 = __bfloat1622float2(*reinterpret_cast<__nv_bfloat162*>(&v.z));
        float2 f3 = __bfloat1622float2(*reinterpret_cast<__nv_bfloat162*>(&v.w));
        acc = fmaf(f0.x, p[j][0], acc);  acc = fmaf(f0.y, p[j][1], acc);
        acc = fmaf(f1.x, p[j][2], acc);  acc = fmaf(f1.y, p[j][3], acc);
        acc = fmaf(f2.x, p[j][4], acc);  acc = fmaf(f2.y, p[j][5], acc);
        acc = fmaf(f3.x, p[j][6], acc);  acc = fmaf(f3.y, p[j][7], acc);
    }
    return acc;
}

// ---------------- Kernel 2: sims + LSE + argmax + tree-fused reduce ---------
__global__ void __launch_bounds__(256)
sim_kernel(float* __restrict__ out, int out_size) {
    int m    = blockIdx.x;
    int tid  = threadIdx.x;
    int warp = tid >> 5, lane = tid & 31;

    __shared__ int   sel[N_CAND];
    __shared__ float sims[N_CAND];

    // ---- negative selection (exact JAX threefry, subkeys constant-folded) --
    if (tid < N_CAND) {
        if (tid == 0) {
            sel[0] = m;
        } else {
            int is64 = g_is64;           // published by gather_norm_kernel
            uint32_t t = (uint32_t)m * 64u + (uint32_t)(tid - 1);
            TFK A = tf2x32_c(SK1.a, SK1.b, 0u, t);
            TFK B = tf2x32_c(SK2.a, SK2.b, 0u, t);
            uint32_t r;
            if (!is64) {
                uint32_t hi = A.a ^ A.b, lo = B.a ^ B.b;
                r = ((hi % SPAN) * 1024u + (lo % SPAN)) % SPAN;
            } else {
                unsigned long long hi = (((unsigned long long)A.a) << 32) | A.b;
                unsigned long long lo = (((unsigned long long)B.a) << 32) | B.b;
                r = (uint32_t)(((hi % 4094ull) * 512ull + (lo % 4094ull)) % 4094ull);
            }
            sel[tid] = (int)r + (((int)r >= m) ? 1 : 0);
        }
    }

    // ---- stage this lane's 16 pred elements into registers ----
    float p[2][8];
    {
        const float4* p4 = (const float4*)(g_pred + (size_t)m * D_DIM);
        #pragma unroll
        for (int j = 0; j < 2; j++) {
            float4 a = p4[j * 64 + lane * 2];
            float4 b = p4[j * 64 + lane * 2 + 1];
            p[j][0] = a.x; p[j][1] = a.y; p[j][2] = a.z; p[j][3] = a.w;
            p[j][4] = b.x; p[j][5] = b.y; p[j][6] = b.z; p[j][7] = b.w;
        }
    }
    __syncthreads();

    // ---- 65 dots, 8 warps, 2 candidates in flight per warp ----
    {
        int c = warp;
        while (c + 8 < N_CAND) {
            const uint4* eA = (const uint4*)(g_enc + (size_t)sel[c]     * D_DIM);
            const uint4* eB = (const uint4*)(g_enc + (size_t)sel[c + 8] * D_DIM);
            float a0 = cand_dot(eA, lane, p);
            float a1 = cand_dot(eB, lane, p);
            #pragma unroll
            for (int o = 16; o; o >>= 1) {
                a0 += __shfl_xor_sync(0xFFFFFFFFu, a0, o);
                a1 += __shfl_xor_sync(0xFFFFFFFFu, a1, o);
            }
            if (lane == 0) { sims[c] = a0 * 10.0f; sims[c + 8] = a1 * 10.0f; }
            c += 16;
        }
        if (c < N_CAND) {
            const uint4* eA = (const uint4*)(g_enc + (size_t)sel[c] * D_DIM);
            float a0 = cand_dot(eA, lane, p);
            #pragma unroll
            for (int o = 16; o; o >>= 1) a0 += __shfl_xor_sync(0xFFFFFFFFu, a0, o);
            if (lane == 0) sims[c] = a0 * 10.0f;
        }
    }
    __syncthreads();

    // ---- warp-parallel LSE / argmax (warp 0) ----
    if (warp == 0) {
        float v0 = sims[lane];
        float v1 = sims[lane + 32];
        float v2 = (lane == 0) ? sims[64] : -3.4e38f;
        float mx = fmaxf(fmaxf(v0, v1), v2);
        #pragma unroll
        for (int o = 16; o; o >>= 1) mx = fmaxf(mx, __shfl_xor_sync(0xFFFFFFFFu, mx, o));
        float s = expf(v0 - mx) + expf(v1 - mx) + ((lane == 0) ? expf(v2 - mx) : 0.0f);
        #pragma unroll
        for (int o = 16; o; o >>= 1) s += __shfl_xor_sync(0xFFFFFFFFu, s, o);
        if (lane == 0) {
            float s0 = sims[0];
            g_rowloss[m] = mx + logf(s) - s0;
            g_rowacc[m]  = (s0 >= mx) ? 1.0f : 0.0f;
        }
    }

    // ---- two-level arrival tree + fused deterministic final reduce ----
    __shared__ bool last;
    __syncthreads();
    __threadfence();
    if (tid == 0) {
        bool l = false;
        if (atomicAdd(&g_cnt1[m >> 6], 1u) == 63u) {
            if (atomicAdd(&g_cnt2, 1u) == 63u) l = true;
        }
        last = l;
    }
    __syncthreads();
    if (!last) return;
    __threadfence();

    // self-reset counters for the next graph replay (all blocks have arrived)
    if (tid < 64) g_cnt1[tid] = 0u;
    if (tid == 64) g_cnt2 = 0u;

    float sl = 0.0f, sa = 0.0f;
    #pragma unroll
    for (int k = 0; k < M_PAIRS / 256; k++) {
        int i = k * 256 + tid;
        sl += g_rowloss[i];
        sa += g_rowacc[i];
    }
    __shared__ float bl[8], ba[8];
    #pragma unroll
    for (int o = 16; o; o >>= 1) {
        sl += __shfl_xor_sync(0xFFFFFFFFu, sl, o);
        sa += __shfl_xor_sync(0xFFFFFFFFu, sa, o);
    }
    if (lane == 0) { bl[warp] = sl; ba[warp] = sa; }
    __syncthreads();
    if (tid == 0) {
        float tl = 0.0f, ta = 0.0f;
        #pragma unroll
        for (int w = 0; w < 8; w++) { tl += bl[w]; ta += ba[w]; }
        out[0] = tl / (float)M_PAIRS;
        if (out_size > 1) out[1] = ta / (float)M_PAIRS;
    }
}

// ---------------- Launch ----------------------------------------------------
extern "C" void kernel_launch(void* const* d_in, const int* in_sizes, int n_in,
                              void* d_out, int out_size) {
    const float* pred = (const float*)d_in[0];
    const float* enc  = (const float*)d_in[1];
    const void*  mask = d_in[2];

    gather_norm_kernel<<<M_PAIRS, 256>>>(pred, enc, mask);
    sim_kernel<<<M_PAIRS, 256>>>((float*)d_out, out_size);
}